// round 5
// baseline (speedup 1.0000x reference)
#include <cuda_runtime.h>
#include <cstdint>
#include <math.h>

// ---------------- problem constants ----------------
namespace cfg {
constexpr int Bb    = 2;
constexpr int Ss    = 4096;
constexpr int DM    = 3584;
constexpr int Hh    = 112;
constexpr int DH    = 64;
constexpr int CHUNK = 256;
constexpr int INNER = Hh * DH;          // 7168
constexpr int M1    = Bb * Ss;          // 8192
constexpr int N1    = 2 * INNER;        // 14336
constexpr int K1    = DM;               // 3584
constexpr int N2    = DM;               // 3584
constexpr int K2    = INNER;            // 7168
constexpr int NCH   = Ss / CHUNK;       // 16
}

// ---------------- scratch (no cudaMalloc allowed) ----------------
__device__ float g_xz[(size_t)cfg::M1 * cfg::N1];   // GEMM1 out (natural order)
__device__ float g_y [(size_t)cfg::M1 * cfg::K2];   // scan out  (k-permuted, tf32-rounded)
__device__ float g_a1[(size_t)cfg::M1 * cfg::K1];   // hs    (k-permuted, tf32-rounded)
__device__ float g_w1[(size_t)cfg::N1 * cfg::K1];   // W_in  (k-permuted, tf32-rounded)
__device__ float g_w2[(size_t)cfg::N2 * cfg::K2];   // W_out (k-permuted, tf32-rounded)

// ---------------- helpers ----------------
__device__ __forceinline__ uint32_t f2tf32(float x) {
    uint32_t u;
    asm("cvt.rna.tf32.f32 %0, %1;" : "=r"(u) : "f"(x));
    return u;
}
__device__ __forceinline__ float rtf32(float x) { return __uint_as_float(f2tf32(x)); }

__device__ __forceinline__ uint32_t smem_u32(const void* p) {
    uint32_t a;
    asm("{ .reg .u64 t; cvta.to.shared.u64 t, %1; cvt.u32.u64 %0, t; }" : "=r"(a) : "l"(p));
    return a;
}
__device__ __forceinline__ void cp_async16(uint32_t smem_addr, const void* gmem) {
    asm volatile("cp.async.cg.shared.global [%0], [%1], 16;" :: "r"(smem_addr), "l"(gmem) : "memory");
}
__device__ __forceinline__ void mma_m16n8k8(float d[4], const uint32_t a[4], const uint32_t b[2]) {
    asm volatile(
        "mma.sync.aligned.m16n8k8.row.col.f32.tf32.tf32.f32 "
        "{%0,%1,%2,%3}, {%4,%5,%6,%7}, {%8,%9}, {%0,%1,%2,%3};"
        : "+f"(d[0]), "+f"(d[1]), "+f"(d[2]), "+f"(d[3])
        : "r"(a[0]), "r"(a[1]), "r"(a[2]), "r"(a[3]),
          "r"(b[0]), "r"(b[1]));
}

// ---------------- tf32 GEMM v3: C[M,N] = A[M,K] * B[N,K]^T ----------------
// Inputs k-permuted in 8-blocks (slot p holds original k=(p>>1)+(p&1)*4)
// => fragment k-pairs (tg, tg+4) adjacent -> LDS.64 fragment loads.
// BM=128, BN=256, BK=16, 4-stage cp.async pipeline, 512 threads (16 warps),
// warp tile 64x32 (2x8 warp grid) -> 4 warps/SMSP for latency hiding.
#define GBM 128
#define GBN 256
#define GBK 16
#define GSTG 4
#define STG_WORDS 6144                      // A 128*16 + B 256*16 floats
#define GSMEM_BYTES (GSTG * STG_WORDS * 4)  // 96 KB

__global__ __launch_bounds__(512, 1)
void gemm_tf32_v3(const float* __restrict__ A, const float* __restrict__ B,
                  float* __restrict__ C, int M, int N, int K)
{
    extern __shared__ float smem[];
    const uint32_t smem_b = smem_u32(smem);

    const int tid  = threadIdx.x;
    const int lane = tid & 31;
    const int wid  = tid >> 5;          // 0..15
    const int gq   = lane >> 2;         // 0..7
    const int tg   = lane & 3;          // 0..3
    const int m_w  = (wid >> 3) * 64;   // 2 warp rows
    const int n_w  = (wid & 7) * 32;    // 8 warp cols

    // ---- tile swizzle (grouped m for L2 reuse) ----
    const int nTm = M / GBM, nTn = N / GBN;
    constexpr int GROUP = 8;
    const int npg     = GROUP * nTn;
    const int gidx    = blockIdx.x / npg;
    const int first_m = gidx * GROUP;
    const int gsz     = min(nTm - first_m, GROUP);
    const int inG     = blockIdx.x % npg;
    const int m0 = (first_m + (inG % gsz)) * GBM;
    const int n0 = (inG / gsz) * GBN;

    // ---- cp.async stage fill (16B granules, XOR-swizzled by row&3) ----
    const int gr  = tid >> 2;           // 0..127
    const int gg  = tid & 3;            // granule 0..3
    const int gsw = gg ^ (gr & 3);      // (row+128)&3 == row&3
    const float* Abase = A + (size_t)(m0 + gr) * K + gg * 4;
    const float* Bbase = B + (size_t)(n0 + gr) * K + gg * 4;

    auto load_stage = [&](int s, int kt) {
        const uint32_t sa = smem_b + s * (STG_WORDS * 4);
        const uint32_t sb = sa + 2048 * 4;
        const float* Ag = Abase + kt * GBK;
        const float* Bg = Bbase + kt * GBK;
        cp_async16(sa + (gr * 16 + gsw * 4) * 4,           Ag);                     // A rows 0..127
        cp_async16(sb + (gr * 16 + gsw * 4) * 4,           Bg);                     // B rows 0..127
        cp_async16(sb + ((gr + 128) * 16 + gsw * 4) * 4,   Bg + (size_t)128 * K);   // B rows 128..255
        asm volatile("cp.async.commit_group;" ::: "memory");
    };

    // prologue: 3 stages in flight
    #pragma unroll
    for (int s = 0; s < GSTG - 1; s++) load_stage(s, s);

    float acc[4][4][4];
    #pragma unroll
    for (int i = 0; i < 4; i++)
        #pragma unroll
        for (int j = 0; j < 4; j++)
            #pragma unroll
            for (int r = 0; r < 4; r++) acc[i][j][r] = 0.f;

    const int nk = K / GBK;
    for (int kt = 0; kt < nk; ++kt) {
        const int s = kt & (GSTG - 1);
        asm volatile("cp.async.wait_group 2;" ::: "memory");
        __syncthreads();

        if (kt + GSTG - 1 < nk) load_stage((kt + GSTG - 1) & (GSTG - 1), kt + GSTG - 1);
        else asm volatile("cp.async.commit_group;" ::: "memory");

        const float* sa = smem + s * STG_WORDS;
        const float* sb = sa + 2048;

        #pragma unroll
        for (int k8 = 0; k8 < 2; ++k8) {
            const int w   = k8 * 8 + tg * 2;   // permuted word pair start
            const int g   = w >> 2;
            const int wib = w & 3;

            uint32_t af[4][4];
            #pragma unroll
            for (int mt = 0; mt < 4; mt++) {
                const int r0 = m_w + mt * 16 + gq;
                const int r1 = r0 + 8;
                const uint2 v0 = *(const uint2*)(sa + r0 * 16 + ((g ^ (r0 & 3)) << 2) + wib);
                const uint2 v1 = *(const uint2*)(sa + r1 * 16 + ((g ^ (r1 & 3)) << 2) + wib);
                af[mt][0] = v0.x; af[mt][2] = v0.y;
                af[mt][1] = v1.x; af[mt][3] = v1.y;
            }
            uint32_t bf[4][2];
            #pragma unroll
            for (int nt = 0; nt < 4; nt++) {
                const int rn = n_w + nt * 8 + gq;
                const uint2 v = *(const uint2*)(sb + rn * 16 + ((g ^ (rn & 3)) << 2) + wib);
                bf[nt][0] = v.x; bf[nt][1] = v.y;
            }
            #pragma unroll
            for (int mt = 0; mt < 4; mt++)
                #pragma unroll
                for (int nt = 0; nt < 4; nt++)
                    mma_m16n8k8(acc[mt][nt], af[mt], bf[nt]);
        }
    }

    // epilogue
    #pragma unroll
    for (int mt = 0; mt < 4; mt++) {
        const int r0 = m0 + m_w + mt * 16 + gq;
        #pragma unroll
        for (int nt = 0; nt < 4; nt++) {
            const int c0 = n0 + n_w + nt * 8 + tg * 2;
            *(float2*)&C[(size_t)r0 * N + c0]       = make_float2(acc[mt][nt][0], acc[mt][nt][1]);
            *(float2*)&C[(size_t)(r0 + 8) * N + c0] = make_float2(acc[mt][nt][2], acc[mt][nt][3]);
        }
    }
}

// ---------------- tf32 round + k-permute (8-block [0,4,1,5,2,6,3,7]) ----------------
__global__ __launch_bounds__(256)
void round_perm_kernel(const float* __restrict__ in, float* __restrict__ out, int n8)
{
    const int i = blockIdx.x * blockDim.x + threadIdx.x;
    if (i >= n8) return;
    const float4 r0 = ((const float4*)in)[2 * i];       // k 0..3
    const float4 r1 = ((const float4*)in)[2 * i + 1];   // k 4..7
    float4 o0, o1;
    o0.x = rtf32(r0.x); o0.y = rtf32(r1.x); o0.z = rtf32(r0.y); o0.w = rtf32(r1.y);
    o1.x = rtf32(r0.z); o1.y = rtf32(r1.z); o1.z = rtf32(r0.w); o1.w = rtf32(r1.w);
    ((float4*)out)[2 * i]     = o0;
    ((float4*)out)[2 * i + 1] = o1;
}

// ---------------- scan + sigmoid gate (reads natural xz, writes permuted+rounded y) ----------------
__global__ __launch_bounds__(256)
void scan_gate_kernel(const float* __restrict__ A_log,
                      const float* __restrict__ xz,
                      float* __restrict__ y)
{
    using namespace cfg;
    const int idx   = blockIdx.x * blockDim.x + threadIdx.x;
    const int inner = idx % INNER;
    const int bt    = idx / INNER;
    const int t     = bt % CHUNK;
    const int b     = bt / CHUNK;

    const float Ah = expf(-fabsf(A_log[inner >> 6]));
    float hstate = 0.f;

    const int k7     = inner & 7;
    const int pinner = (inner & ~7) + ((k7 & 3) * 2) + (k7 >> 2);

    size_t xrow = ((size_t)b * Ss + t) * (size_t)N1 + inner;
    size_t yrow = ((size_t)b * Ss + t) * (size_t)INNER + pinner;
    const size_t xstep = (size_t)CHUNK * N1;
    const size_t ystep = (size_t)CHUNK * INNER;

    #pragma unroll
    for (int c = 0; c < NCH; c++) {
        const float xv = xz[xrow];
        const float zv = xz[xrow + INNER];
        hstate = hstate * Ah + 0.1f * xv;
        const float sig = 1.f / (1.f + expf(-zv));
        y[yrow] = rtf32(hstate * sig);
        xrow += xstep;
        yrow += ystep;
    }
}

// ---------------- launch ----------------
extern "C" void kernel_launch(void* const* d_in, const int* in_sizes, int n_in,
                              void* d_out, int out_size)
{
    using namespace cfg;
    const float* hs    = (const float*)d_in[0];
    const float* W_in  = (const float*)d_in[1];
    const float* W_out = (const float*)d_in[2];
    const float* A_log = (const float*)d_in[3];
    float* out = (float*)d_out;

    float *xz, *y, *a1, *w1, *w2;
    cudaGetSymbolAddress((void**)&xz, g_xz);
    cudaGetSymbolAddress((void**)&y,  g_y);
    cudaGetSymbolAddress((void**)&a1, g_a1);
    cudaGetSymbolAddress((void**)&w1, g_w1);
    cudaGetSymbolAddress((void**)&w2, g_w2);

    cudaFuncSetAttribute(gemm_tf32_v3, cudaFuncAttributeMaxDynamicSharedMemorySize, GSMEM_BYTES);

    // round to tf32 + k-permute all GEMM operands
    {
        int n8;
        n8 = (M1 * K1) / 8; round_perm_kernel<<<(n8 + 255) / 256, 256>>>(hs,    a1, n8);
        n8 = (N1 * K1) / 8; round_perm_kernel<<<(n8 + 255) / 256, 256>>>(W_in,  w1, n8);
        n8 = (N2 * K2) / 8; round_perm_kernel<<<(n8 + 255) / 256, 256>>>(W_out, w2, n8);
    }

    // GEMM1: xz = hs @ W_in^T   (M=8192, N=14336, K=3584)
    gemm_tf32_v3<<<(M1 / GBM) * (N1 / GBN), 512, GSMEM_BYTES>>>(a1, w1, xz, M1, N1, K1);

    // scan + gate (writes permuted y)
    const int total = Bb * CHUNK * INNER;
    scan_gate_kernel<<<total / 256, 256>>>(A_log, xz, y);

    // GEMM2: out = y @ W_out^T  (M=8192, N=3584, K=7168)
    gemm_tf32_v3<<<(M1 / GBM) * (N2 / GBN), 512, GSMEM_BYTES>>>(y, w2, out, M1, N2, K2);
}

// round 6
// speedup vs baseline: 1.0634x; 1.0634x over previous
#include <cuda_runtime.h>
#include <cstdint>
#include <math.h>

// ---------------- problem constants ----------------
namespace cfg {
constexpr int Bb    = 2;
constexpr int Ss    = 4096;
constexpr int DM    = 3584;
constexpr int Hh    = 112;
constexpr int DH    = 64;
constexpr int CHUNK = 256;
constexpr int INNER = Hh * DH;          // 7168
constexpr int M1    = Bb * Ss;          // 8192
constexpr int N1    = 2 * INNER;        // 14336
constexpr int K1    = DM;               // 3584
constexpr int N2    = DM;               // 3584
constexpr int K2    = INNER;            // 7168
constexpr int NCH   = Ss / CHUNK;       // 16
}

// ---------------- scratch (no cudaMalloc allowed) ----------------
__device__ float g_xz[(size_t)cfg::M1 * cfg::N1];   // GEMM1 out (natural order)
__device__ float g_y [(size_t)cfg::M1 * cfg::K2];   // scan out  (k-permuted, tf32-rounded)
__device__ float g_a1[(size_t)cfg::M1 * cfg::K1];   // hs    (k-permuted, tf32-rounded)
__device__ float g_w1[(size_t)cfg::N1 * cfg::K1];   // W_in  (k-permuted, tf32-rounded)
__device__ float g_w2[(size_t)cfg::N2 * cfg::K2];   // W_out (k-permuted, tf32-rounded)

// ---------------- helpers ----------------
__device__ __forceinline__ uint32_t f2tf32(float x) {
    uint32_t u;
    asm("cvt.rna.tf32.f32 %0, %1;" : "=r"(u) : "f"(x));
    return u;
}
__device__ __forceinline__ float rtf32(float x) { return __uint_as_float(f2tf32(x)); }

__device__ __forceinline__ uint32_t smem_u32(const void* p) {
    uint32_t a;
    asm("{ .reg .u64 t; cvta.to.shared.u64 t, %1; cvt.u32.u64 %0, t; }" : "=r"(a) : "l"(p));
    return a;
}
__device__ __forceinline__ void cp_async16(uint32_t smem_addr, const void* gmem) {
    asm volatile("cp.async.cg.shared.global [%0], [%1], 16;" :: "r"(smem_addr), "l"(gmem) : "memory");
}
__device__ __forceinline__ void mma_m16n8k8(float d[4], const uint32_t a[4], const uint32_t b[2]) {
    asm volatile(
        "mma.sync.aligned.m16n8k8.row.col.f32.tf32.tf32.f32 "
        "{%0,%1,%2,%3}, {%4,%5,%6,%7}, {%8,%9}, {%0,%1,%2,%3};"
        : "+f"(d[0]), "+f"(d[1]), "+f"(d[2]), "+f"(d[3])
        : "r"(a[0]), "r"(a[1]), "r"(a[2]), "r"(a[3]),
          "r"(b[0]), "r"(b[1]));
}

// ---------------- tf32 GEMM v4: C[M,N] = A[M,K] * B[N,K]^T ----------------
// k-permuted inputs (8-blocks, slot p holds k=(p>>1)+(p&1)*4) -> LDS.64 frag loads.
// BM=128, BN=256, BK=32 per stage (2x 16-wide sub-blocks), 4-stage cp.async
// pipeline (192 KB), 256 threads, 8 warps 2x4 (warp tile 64x64).
// Register double-buffered fragments: one barrier per 32-K, LDS latency hidden
// behind the previous k8's MMA burst.
#define GBM 128
#define GBN 256
#define SUB_WORDS 6144                       // one 16-wide sub-block (A 128x16 + B 256x16)
#define STG_WORDS (2 * SUB_WORDS)            // 48 KB stage (BK=32)
#define GSTG 4
#define GSMEM_BYTES (GSTG * STG_WORDS * 4)   // 192 KB

__global__ __launch_bounds__(256, 1)
void gemm_tf32_v4(const float* __restrict__ A, const float* __restrict__ B,
                  float* __restrict__ C, int M, int N, int K)
{
    extern __shared__ float smem[];
    const uint32_t smem_b = smem_u32(smem);

    const int tid  = threadIdx.x;
    const int lane = tid & 31;
    const int wid  = tid >> 5;          // 0..7
    const int gq   = lane >> 2;         // 0..7
    const int tg   = lane & 3;          // 0..3
    const int m_w  = (wid >> 2) * 64;   // 2 warp rows
    const int n_w  = (wid & 3) * 64;    // 4 warp cols

    // ---- tile swizzle (grouped m for L2 reuse) ----
    const int nTm = M / GBM, nTn = N / GBN;
    constexpr int GROUP = 8;
    const int npg     = GROUP * nTn;
    const int gidx    = blockIdx.x / npg;
    const int first_m = gidx * GROUP;
    const int gsz     = min(nTm - first_m, GROUP);
    const int inG     = blockIdx.x % npg;
    const int m0 = (first_m + (inG % gsz)) * GBM;
    const int n0 = (inG / gsz) * GBN;

    // ---- cp.async fill mapping (16B granules, XOR-swizzled by row&3) ----
    const int gr  = tid >> 2;           // 0..63
    const int gg  = tid & 3;            // 0..3
    const int gsw = gg ^ (gr & 3);
    const float* Abase = A + (size_t)(m0 + gr) * K + gg * 4;
    const float* Bbase = B + (size_t)(n0 + gr) * K + gg * 4;

    auto load_stage = [&](int slot, int st) {
        const uint32_t sbb = smem_b + slot * (STG_WORDS * 4);
        #pragma unroll
        for (int s2 = 0; s2 < 2; s2++) {
            const uint32_t sa = sbb + s2 * (SUB_WORDS * 4);
            const uint32_t sb = sa + 2048 * 4;
            const float* Ag = Abase + st * 32 + s2 * 16;
            const float* Bg = Bbase + st * 32 + s2 * 16;
            cp_async16(sa + (gr * 16 + gsw * 4) * 4,          Ag);
            cp_async16(sa + ((gr + 64) * 16 + gsw * 4) * 4,   Ag + (size_t)64 * K);
            #pragma unroll
            for (int j = 0; j < 4; j++)
                cp_async16(sb + ((gr + j * 64) * 16 + gsw * 4) * 4, Bg + (size_t)(j * 64) * K);
        }
        asm volatile("cp.async.commit_group;" ::: "memory");
    };

    // prologue: 3 stages in flight
    #pragma unroll
    for (int s = 0; s < GSTG - 1; s++) load_stage(s, s);

    float acc[4][8][4];
    #pragma unroll
    for (int i = 0; i < 4; i++)
        #pragma unroll
        for (int j = 0; j < 8; j++)
            #pragma unroll
            for (int r = 0; r < 4; r++) acc[i][j][r] = 0.f;

    uint32_t af[2][4][4];
    uint32_t bf[2][8][2];

    auto ldfrag = [&](int buf, const float* sa, const float* sb, int k8p) {
        const int w   = k8p * 8 + tg * 2;
        const int g   = w >> 2;
        const int wib = w & 3;
        #pragma unroll
        for (int mt = 0; mt < 4; mt++) {
            const int r0 = m_w + mt * 16 + gq;
            const int r1 = r0 + 8;
            const uint2 v0 = *(const uint2*)(sa + r0 * 16 + ((g ^ (r0 & 3)) << 2) + wib);
            const uint2 v1 = *(const uint2*)(sa + r1 * 16 + ((g ^ (r1 & 3)) << 2) + wib);
            af[buf][mt][0] = v0.x; af[buf][mt][2] = v0.y;
            af[buf][mt][1] = v1.x; af[buf][mt][3] = v1.y;
        }
        #pragma unroll
        for (int nt = 0; nt < 8; nt++) {
            const int rn = n_w + nt * 8 + gq;
            const uint2 v = *(const uint2*)(sb + rn * 16 + ((g ^ (rn & 3)) << 2) + wib);
            bf[buf][nt][0] = v.x; bf[buf][nt][1] = v.y;
        }
    };

    const int nst = K / 32;
    for (int st = 0; st < nst; ++st) {
        asm volatile("cp.async.wait_group 2;" ::: "memory");
        __syncthreads();

        if (st + GSTG - 1 < nst) load_stage((st + GSTG - 1) & (GSTG - 1), st + GSTG - 1);
        else asm volatile("cp.async.commit_group;" ::: "memory");

        const float* sbase = smem + (st & (GSTG - 1)) * STG_WORDS;

        // software-pipelined fragment loads across 4 k8 steps
        ldfrag(0, sbase, sbase + 2048, 0);
        #pragma unroll
        for (int k8 = 0; k8 < 4; ++k8) {
            if (k8 < 3) {
                const float* sa2 = sbase + ((k8 + 1) >> 1) * SUB_WORDS;
                ldfrag((k8 + 1) & 1, sa2, sa2 + 2048, (k8 + 1) & 1);
            }
            const int buf = k8 & 1;
            #pragma unroll
            for (int mt = 0; mt < 4; mt++)
                #pragma unroll
                for (int nt = 0; nt < 8; nt++)
                    mma_m16n8k8(acc[mt][nt], af[buf][mt], bf[buf][nt]);
        }
    }

    // epilogue
    #pragma unroll
    for (int mt = 0; mt < 4; mt++) {
        const int r0 = m0 + m_w + mt * 16 + gq;
        #pragma unroll
        for (int nt = 0; nt < 8; nt++) {
            const int c0 = n0 + n_w + nt * 8 + tg * 2;
            *(float2*)&C[(size_t)r0 * N + c0]       = make_float2(acc[mt][nt][0], acc[mt][nt][1]);
            *(float2*)&C[(size_t)(r0 + 8) * N + c0] = make_float2(acc[mt][nt][2], acc[mt][nt][3]);
        }
    }
}

// ---------------- tf32 round + k-permute (8-block [0,4,1,5,2,6,3,7]) ----------------
__global__ __launch_bounds__(256)
void round_perm_kernel(const float* __restrict__ in, float* __restrict__ out, int n8)
{
    const int i = blockIdx.x * blockDim.x + threadIdx.x;
    if (i >= n8) return;
    const float4 r0 = ((const float4*)in)[2 * i];       // k 0..3
    const float4 r1 = ((const float4*)in)[2 * i + 1];   // k 4..7
    float4 o0, o1;
    o0.x = rtf32(r0.x); o0.y = rtf32(r1.x); o0.z = rtf32(r0.y); o0.w = rtf32(r1.y);
    o1.x = rtf32(r0.z); o1.y = rtf32(r1.z); o1.z = rtf32(r0.w); o1.w = rtf32(r1.w);
    ((float4*)out)[2 * i]     = o0;
    ((float4*)out)[2 * i + 1] = o1;
}

// ---------------- scan + sigmoid gate (reads natural xz, writes permuted+rounded y) ----------------
__global__ __launch_bounds__(256)
void scan_gate_kernel(const float* __restrict__ A_log,
                      const float* __restrict__ xz,
                      float* __restrict__ y)
{
    using namespace cfg;
    const int idx   = blockIdx.x * blockDim.x + threadIdx.x;
    const int inner = idx % INNER;
    const int bt    = idx / INNER;
    const int t     = bt % CHUNK;
    const int b     = bt / CHUNK;

    const float Ah = expf(-fabsf(A_log[inner >> 6]));
    float hstate = 0.f;

    const int k7     = inner & 7;
    const int pinner = (inner & ~7) + ((k7 & 3) * 2) + (k7 >> 2);

    size_t xrow = ((size_t)b * Ss + t) * (size_t)N1 + inner;
    size_t yrow = ((size_t)b * Ss + t) * (size_t)INNER + pinner;
    const size_t xstep = (size_t)CHUNK * N1;
    const size_t ystep = (size_t)CHUNK * INNER;

    #pragma unroll
    for (int c = 0; c < NCH; c++) {
        const float xv = xz[xrow];
        const float zv = xz[xrow + INNER];
        hstate = hstate * Ah + 0.1f * xv;
        const float sig = 1.f / (1.f + expf(-zv));
        y[yrow] = rtf32(hstate * sig);
        xrow += xstep;
        yrow += ystep;
    }
}

// ---------------- launch ----------------
extern "C" void kernel_launch(void* const* d_in, const int* in_sizes, int n_in,
                              void* d_out, int out_size)
{
    using namespace cfg;
    const float* hs    = (const float*)d_in[0];
    const float* W_in  = (const float*)d_in[1];
    const float* W_out = (const float*)d_in[2];
    const float* A_log = (const float*)d_in[3];
    float* out = (float*)d_out;

    float *xz, *y, *a1, *w1, *w2;
    cudaGetSymbolAddress((void**)&xz, g_xz);
    cudaGetSymbolAddress((void**)&y,  g_y);
    cudaGetSymbolAddress((void**)&a1, g_a1);
    cudaGetSymbolAddress((void**)&w1, g_w1);
    cudaGetSymbolAddress((void**)&w2, g_w2);

    cudaFuncSetAttribute(gemm_tf32_v4, cudaFuncAttributeMaxDynamicSharedMemorySize, GSMEM_BYTES);

    // round to tf32 + k-permute all GEMM operands
    {
        int n8;
        n8 = (M1 * K1) / 8; round_perm_kernel<<<(n8 + 255) / 256, 256>>>(hs,    a1, n8);
        n8 = (N1 * K1) / 8; round_perm_kernel<<<(n8 + 255) / 256, 256>>>(W_in,  w1, n8);
        n8 = (N2 * K2) / 8; round_perm_kernel<<<(n8 + 255) / 256, 256>>>(W_out, w2, n8);
    }

    // GEMM1: xz = hs @ W_in^T   (M=8192, N=14336, K=3584)
    gemm_tf32_v4<<<(M1 / GBM) * (N1 / GBN), 256, GSMEM_BYTES>>>(a1, w1, xz, M1, N1, K1);

    // scan + gate (writes permuted y)
    const int total = Bb * CHUNK * INNER;
    scan_gate_kernel<<<total / 256, 256>>>(A_log, xz, y);

    // GEMM2: out = y @ W_out^T  (M=8192, N=3584, K=7168)
    gemm_tf32_v4<<<(M1 / GBM) * (N2 / GBN), 256, GSMEM_BYTES>>>(y, w2, out, M1, N2, K2);
}

// round 7
// speedup vs baseline: 1.1189x; 1.0522x over previous
#include <cuda_runtime.h>
#include <cstdint>
#include <math.h>

// ---------------- problem constants ----------------
namespace cfg {
constexpr int Bb    = 2;
constexpr int Ss    = 4096;
constexpr int DM    = 3584;
constexpr int Hh    = 112;
constexpr int DH    = 64;
constexpr int CHUNK = 256;
constexpr int INNER = Hh * DH;          // 7168
constexpr int M1    = Bb * Ss;          // 8192
constexpr int N1    = 2 * INNER;        // 14336
constexpr int K1    = DM;               // 3584
constexpr int N2    = DM;               // 3584
constexpr int K2    = INNER;            // 7168
constexpr int NCH   = Ss / CHUNK;       // 16
}

// ---------------- scratch (no cudaMalloc allowed) ----------------
__device__ float g_xz[(size_t)cfg::M1 * cfg::N1];   // GEMM1 out (natural order)
__device__ float g_y [(size_t)cfg::M1 * cfg::K2];   // scan out  (k-permuted, tf32-rounded)
__device__ float g_a1[(size_t)cfg::M1 * cfg::K1];   // hs    (k-permuted, tf32-rounded)
__device__ float g_w1[(size_t)cfg::N1 * cfg::K1];   // W_in  (k-permuted, tf32-rounded)
__device__ float g_w2[(size_t)cfg::N2 * cfg::K2];   // W_out (k-permuted, tf32-rounded)

// ---------------- helpers ----------------
__device__ __forceinline__ uint32_t f2tf32(float x) {
    uint32_t u;
    asm("cvt.rna.tf32.f32 %0, %1;" : "=r"(u) : "f"(x));
    return u;
}
__device__ __forceinline__ float rtf32(float x) { return __uint_as_float(f2tf32(x)); }

__device__ __forceinline__ uint32_t smem_u32(const void* p) {
    uint32_t a;
    asm("{ .reg .u64 t; cvta.to.shared.u64 t, %1; cvt.u32.u64 %0, t; }" : "=r"(a) : "l"(p));
    return a;
}
__device__ __forceinline__ void cp_async16(uint32_t smem_addr, const void* gmem) {
    asm volatile("cp.async.cg.shared.global [%0], [%1], 16;" :: "r"(smem_addr), "l"(gmem) : "memory");
}
__device__ __forceinline__ void mma_m16n8k8(float d[4], const uint32_t a[4], const uint32_t b[2]) {
    asm volatile(
        "mma.sync.aligned.m16n8k8.row.col.f32.tf32.tf32.f32 "
        "{%0,%1,%2,%3}, {%4,%5,%6,%7}, {%8,%9}, {%0,%1,%2,%3};"
        : "+f"(d[0]), "+f"(d[1]), "+f"(d[2]), "+f"(d[3])
        : "r"(a[0]), "r"(a[1]), "r"(a[2]), "r"(a[3]),
          "r"(b[0]), "r"(b[1]));
}

// ---------------- tf32 GEMM v5: C[M,N] = A[M,K] * B[N,K]^T ----------------
// k-permuted inputs (8-blocks, slot p holds k=(p>>1)+(p&1)*4) -> LDS.64 frag loads.
// BM=128, BN=128, BK=32 per stage, 3-stage cp.async pipeline (96 KB),
// 256 threads, 8 warps 2x4 (warp tile 64x32), __launch_bounds__(256,2)
// => 2 CTAs/SM: independent barrier domains overlap each other's stalls.
#define GBM 128
#define GBN 128
#define SUB_WORDS 4096                       // 16-wide sub-block: A 128x16 + B 128x16
#define STG_WORDS (2 * SUB_WORDS)            // 32 KB stage (BK=32)
#define GSTG 3
#define GSMEM_BYTES (GSTG * STG_WORDS * 4)   // 96 KB

__global__ __launch_bounds__(256, 2)
void gemm_tf32_v5(const float* __restrict__ A, const float* __restrict__ B,
                  float* __restrict__ C, int M, int N, int K)
{
    extern __shared__ float smem[];
    const uint32_t smem_b = smem_u32(smem);

    const int tid  = threadIdx.x;
    const int lane = tid & 31;
    const int wid  = tid >> 5;          // 0..7
    const int gq   = lane >> 2;         // 0..7
    const int tg   = lane & 3;          // 0..3
    const int m_w  = (wid >> 2) * 64;   // 2 warp rows
    const int n_w  = (wid & 3) * 32;    // 4 warp cols

    // ---- tile swizzle (grouped m for L2 reuse) ----
    const int nTm = M / GBM, nTn = N / GBN;
    constexpr int GROUP = 8;
    const int npg     = GROUP * nTn;
    const int gidx    = blockIdx.x / npg;
    const int first_m = gidx * GROUP;
    const int gsz     = min(nTm - first_m, GROUP);
    const int inG     = blockIdx.x % npg;
    const int m0 = (first_m + (inG % gsz)) * GBM;
    const int n0 = (inG / gsz) * GBN;

    // ---- cp.async fill mapping (16B granules, XOR-swizzled by row&3) ----
    const int gr  = tid >> 2;           // 0..63
    const int gg  = tid & 3;            // 0..3
    const int gsw = gg ^ (gr & 3);
    const float* Abase = A + (size_t)(m0 + gr) * K + gg * 4;
    const float* Bbase = B + (size_t)(n0 + gr) * K + gg * 4;

    auto load_stage = [&](int slot, int st) {
        const uint32_t sbb = smem_b + slot * (STG_WORDS * 4);
        #pragma unroll
        for (int s2 = 0; s2 < 2; s2++) {
            const uint32_t sa = sbb + s2 * (SUB_WORDS * 4);
            const uint32_t sb = sa + 2048 * 4;
            const float* Ag = Abase + st * 32 + s2 * 16;
            const float* Bg = Bbase + st * 32 + s2 * 16;
            cp_async16(sa + (gr * 16 + gsw * 4) * 4,          Ag);
            cp_async16(sa + ((gr + 64) * 16 + gsw * 4) * 4,   Ag + (size_t)64 * K);
            cp_async16(sb + (gr * 16 + gsw * 4) * 4,          Bg);
            cp_async16(sb + ((gr + 64) * 16 + gsw * 4) * 4,   Bg + (size_t)64 * K);
        }
        asm volatile("cp.async.commit_group;" ::: "memory");
    };

    // prologue: 2 stages in flight
    #pragma unroll
    for (int s = 0; s < GSTG - 1; s++) load_stage(s, s);

    float acc[4][4][4];
    #pragma unroll
    for (int i = 0; i < 4; i++)
        #pragma unroll
        for (int j = 0; j < 4; j++)
            #pragma unroll
            for (int r = 0; r < 4; r++) acc[i][j][r] = 0.f;

    uint32_t af[2][4][4];
    uint32_t bf[2][4][2];

    auto ldfrag = [&](int buf, const float* sa, const float* sb, int k8p) {
        const int w   = k8p * 8 + tg * 2;
        const int g   = w >> 2;
        const int wib = w & 3;
        #pragma unroll
        for (int mt = 0; mt < 4; mt++) {
            const int r0 = m_w + mt * 16 + gq;
            const int r1 = r0 + 8;
            const uint2 v0 = *(const uint2*)(sa + r0 * 16 + ((g ^ (r0 & 3)) << 2) + wib);
            const uint2 v1 = *(const uint2*)(sa + r1 * 16 + ((g ^ (r1 & 3)) << 2) + wib);
            af[buf][mt][0] = v0.x; af[buf][mt][2] = v0.y;
            af[buf][mt][1] = v1.x; af[buf][mt][3] = v1.y;
        }
        #pragma unroll
        for (int nt = 0; nt < 4; nt++) {
            const int rn = n_w + nt * 8 + gq;
            const uint2 v = *(const uint2*)(sb + rn * 16 + ((g ^ (rn & 3)) << 2) + wib);
            bf[buf][nt][0] = v.x; bf[buf][nt][1] = v.y;
        }
    };

    const int nst = K / 32;
    for (int st = 0; st < nst; ++st) {
        asm volatile("cp.async.wait_group 1;" ::: "memory");
        __syncthreads();

        int slot = st % GSTG;
        if (st + GSTG - 1 < nst) load_stage((st + GSTG - 1) % GSTG, st + GSTG - 1);
        else asm volatile("cp.async.commit_group;" ::: "memory");

        const float* sbase = smem + slot * STG_WORDS;

        // software-pipelined fragment loads across 4 k8 steps
        ldfrag(0, sbase, sbase + 2048, 0);
        #pragma unroll
        for (int k8 = 0; k8 < 4; ++k8) {
            if (k8 < 3) {
                const float* sa2 = sbase + ((k8 + 1) >> 1) * SUB_WORDS;
                ldfrag((k8 + 1) & 1, sa2, sa2 + 2048, (k8 + 1) & 1);
            }
            const int buf = k8 & 1;
            #pragma unroll
            for (int mt = 0; mt < 4; mt++)
                #pragma unroll
                for (int nt = 0; nt < 4; nt++)
                    mma_m16n8k8(acc[mt][nt], af[buf][mt], bf[buf][nt]);
        }
    }

    // epilogue
    #pragma unroll
    for (int mt = 0; mt < 4; mt++) {
        const int r0 = m0 + m_w + mt * 16 + gq;
        #pragma unroll
        for (int nt = 0; nt < 4; nt++) {
            const int c0 = n0 + n_w + nt * 8 + tg * 2;
            *(float2*)&C[(size_t)r0 * N + c0]       = make_float2(acc[mt][nt][0], acc[mt][nt][1]);
            *(float2*)&C[(size_t)(r0 + 8) * N + c0] = make_float2(acc[mt][nt][2], acc[mt][nt][3]);
        }
    }
}

// ---------------- tf32 round + k-permute (8-block [0,4,1,5,2,6,3,7]) ----------------
__global__ __launch_bounds__(256)
void round_perm_kernel(const float* __restrict__ in, float* __restrict__ out, int n8)
{
    const int i = blockIdx.x * blockDim.x + threadIdx.x;
    if (i >= n8) return;
    const float4 r0 = ((const float4*)in)[2 * i];       // k 0..3
    const float4 r1 = ((const float4*)in)[2 * i + 1];   // k 4..7
    float4 o0, o1;
    o0.x = rtf32(r0.x); o0.y = rtf32(r1.x); o0.z = rtf32(r0.y); o0.w = rtf32(r1.y);
    o1.x = rtf32(r0.z); o1.y = rtf32(r1.z); o1.z = rtf32(r0.w); o1.w = rtf32(r1.w);
    ((float4*)out)[2 * i]     = o0;
    ((float4*)out)[2 * i + 1] = o1;
}

// ---------------- scan + sigmoid gate (reads natural xz, writes permuted+rounded y) ----------------
__global__ __launch_bounds__(256)
void scan_gate_kernel(const float* __restrict__ A_log,
                      const float* __restrict__ xz,
                      float* __restrict__ y)
{
    using namespace cfg;
    const int idx   = blockIdx.x * blockDim.x + threadIdx.x;
    const int inner = idx % INNER;
    const int bt    = idx / INNER;
    const int t     = bt % CHUNK;
    const int b     = bt / CHUNK;

    const float Ah = expf(-fabsf(A_log[inner >> 6]));
    float hstate = 0.f;

    const int k7     = inner & 7;
    const int pinner = (inner & ~7) + ((k7 & 3) * 2) + (k7 >> 2);

    size_t xrow = ((size_t)b * Ss + t) * (size_t)N1 + inner;
    size_t yrow = ((size_t)b * Ss + t) * (size_t)INNER + pinner;
    const size_t xstep = (size_t)CHUNK * N1;
    const size_t ystep = (size_t)CHUNK * INNER;

    #pragma unroll
    for (int c = 0; c < NCH; c++) {
        const float xv = xz[xrow];
        const float zv = xz[xrow + INNER];
        hstate = hstate * Ah + 0.1f * xv;
        const float sig = 1.f / (1.f + expf(-zv));
        y[yrow] = rtf32(hstate * sig);
        xrow += xstep;
        yrow += ystep;
    }
}

// ---------------- launch ----------------
extern "C" void kernel_launch(void* const* d_in, const int* in_sizes, int n_in,
                              void* d_out, int out_size)
{
    using namespace cfg;
    const float* hs    = (const float*)d_in[0];
    const float* W_in  = (const float*)d_in[1];
    const float* W_out = (const float*)d_in[2];
    const float* A_log = (const float*)d_in[3];
    float* out = (float*)d_out;

    float *xz, *y, *a1, *w1, *w2;
    cudaGetSymbolAddress((void**)&xz, g_xz);
    cudaGetSymbolAddress((void**)&y,  g_y);
    cudaGetSymbolAddress((void**)&a1, g_a1);
    cudaGetSymbolAddress((void**)&w1, g_w1);
    cudaGetSymbolAddress((void**)&w2, g_w2);

    cudaFuncSetAttribute(gemm_tf32_v5, cudaFuncAttributeMaxDynamicSharedMemorySize, GSMEM_BYTES);

    // round to tf32 + k-permute all GEMM operands
    {
        int n8;
        n8 = (M1 * K1) / 8; round_perm_kernel<<<(n8 + 255) / 256, 256>>>(hs,    a1, n8);
        n8 = (N1 * K1) / 8; round_perm_kernel<<<(n8 + 255) / 256, 256>>>(W_in,  w1, n8);
        n8 = (N2 * K2) / 8; round_perm_kernel<<<(n8 + 255) / 256, 256>>>(W_out, w2, n8);
    }

    // GEMM1: xz = hs @ W_in^T   (M=8192, N=14336, K=3584)
    gemm_tf32_v5<<<(M1 / GBM) * (N1 / GBN), 256, GSMEM_BYTES>>>(a1, w1, xz, M1, N1, K1);

    // scan + gate (writes permuted y)
    const int total = Bb * CHUNK * INNER;
    scan_gate_kernel<<<total / 256, 256>>>(A_log, xz, y);

    // GEMM2: out = y @ W_out^T  (M=8192, N=3584, K=7168)
    gemm_tf32_v5<<<(M1 / GBM) * (N2 / GBN), 256, GSMEM_BYTES>>>(y, w2, out, M1, N2, K2);
}

// round 9
// speedup vs baseline: 2.4374x; 2.1784x over previous
#include <cuda_runtime.h>
#include <cuda_fp16.h>
#include <cstdint>
#include <math.h>

// ---------------- problem constants ----------------
namespace cfg {
constexpr int Bb    = 2;
constexpr int Ss    = 4096;
constexpr int DM    = 3584;
constexpr int Hh    = 112;
constexpr int DH    = 64;
constexpr int CHUNK = 256;
constexpr int INNER = Hh * DH;          // 7168
constexpr int M1    = Bb * Ss;          // 8192
constexpr int N1    = 2 * INNER;        // 14336
constexpr int K1    = DM;               // 3584
constexpr int N2    = DM;               // 3584
constexpr int K2    = INNER;            // 7168
constexpr int NCH   = Ss / CHUNK;       // 16
}

// ---------------- scratch (no cudaMalloc allowed) ----------------
__device__ float  g_xz [(size_t)cfg::M1 * cfg::N1];  // GEMM1 out (fp32)
__device__ __half g_yh [(size_t)cfg::M1 * cfg::K2];  // scan out (fp16)
__device__ __half g_a1h[(size_t)cfg::M1 * cfg::K1];  // hs    (fp16)
__device__ __half g_w1h[(size_t)cfg::N1 * cfg::K1];  // W_in  (fp16)
__device__ __half g_w2h[(size_t)cfg::N2 * cfg::K2];  // W_out (fp16)

// ---------------- helpers ----------------
__device__ __forceinline__ uint32_t smem_u32(const void* p) {
    uint32_t a;
    asm("{ .reg .u64 t; cvta.to.shared.u64 t, %1; cvt.u32.u64 %0, t; }" : "=r"(a) : "l"(p));
    return a;
}
__device__ __forceinline__ void cp_async16(uint32_t smem_addr, const void* gmem) {
    asm volatile("cp.async.cg.shared.global [%0], [%1], 16;" :: "r"(smem_addr), "l"(gmem) : "memory");
}
__device__ __forceinline__ void ldsm_x4(uint32_t& r0, uint32_t& r1, uint32_t& r2, uint32_t& r3,
                                        uint32_t addr) {
    asm volatile("ldmatrix.sync.aligned.m8n8.x4.shared.b16 {%0,%1,%2,%3}, [%4];"
                 : "=r"(r0), "=r"(r1), "=r"(r2), "=r"(r3) : "r"(addr));
}
__device__ __forceinline__ void mma_f16_16816(float d[4], const uint32_t a[4], const uint32_t b[2]) {
    asm volatile(
        "mma.sync.aligned.m16n8k16.row.col.f32.f16.f16.f32 "
        "{%0,%1,%2,%3}, {%4,%5,%6,%7}, {%8,%9}, {%0,%1,%2,%3};"
        : "+f"(d[0]), "+f"(d[1]), "+f"(d[2]), "+f"(d[3])
        : "r"(a[0]), "r"(a[1]), "r"(a[2]), "r"(a[3]),
          "r"(b[0]), "r"(b[1]));
}
__device__ __forceinline__ uint32_t h2_bits(__half2 h) {
    union { __half2 h; uint32_t u; } cvt;
    cvt.h = h;
    return cvt.u;
}

// ---------------- fp16 GEMM: C[M,N] = A[M,K] * B[N,K]^T (A,B fp16; C fp32) ----------------
// BM=128, BN=128, BK=64 (128B rows, XOR-16B swizzle), 3-stage cp.async (96 KB),
// 256 threads, 8 warps 2x4 (warp tile 64x32), 2 CTAs/SM.
// Fragments via ldmatrix.x4; k16 steps register double-buffered.
#define GBM 128
#define GBN 128
#define GBK 64
#define STG_BYTES 32768                      // A 16KB + B 16KB
#define GSTG 3
#define GSMEM_BYTES (GSTG * STG_BYTES)       // 96 KB

__global__ __launch_bounds__(256, 2)
void gemm_f16(const __half* __restrict__ A, const __half* __restrict__ B,
              float* __restrict__ C, int M, int N, int K)
{
    extern __shared__ char smem[];
    const uint32_t smem_b = smem_u32(smem);

    const int tid  = threadIdx.x;
    const int lane = tid & 31;
    const int wid  = tid >> 5;          // 0..7
    const int gq   = lane >> 2;         // 0..7
    const int tg   = lane & 3;          // 0..3
    const int m_w  = (wid >> 2) * 64;   // 2 warp rows
    const int n_w  = (wid & 3) * 32;    // 4 warp cols

    // ---- tile swizzle (grouped m for L2 reuse) ----
    const int nTm = M / GBM, nTn = N / GBN;
    constexpr int GROUP = 8;
    const int npg     = GROUP * nTn;
    const int gidx    = blockIdx.x / npg;
    const int first_m = gidx * GROUP;
    const int gsz     = min(nTm - first_m, GROUP);
    const int inG     = blockIdx.x % npg;
    const int m0 = (first_m + (inG % gsz)) * GBM;
    const int n0 = (inG / gsz) * GBN;

    // ---- cp.async fill mapping: 16B granules (8 fp16), 8 per 128B row ----
    const __half* Abase = A + (size_t)m0 * K;
    const __half* Bbase = B + (size_t)n0 * K;

    auto load_stage = [&](int slot, int st) {
        const uint32_t sa = smem_b + slot * STG_BYTES;
        const uint32_t sb = sa + 16384;
        const __half* Ag = Abase + st * GBK;
        const __half* Bg = Bbase + st * GBK;
        #pragma unroll
        for (int p = 0; p < 4; p++) {
            const int idx = tid + p * 256;      // 0..1023 granule id
            const int row = idx >> 3;           // 0..127
            const int g   = idx & 7;
            const int gs  = g ^ (row & 7);
            const uint32_t doff = (uint32_t)(row * 128 + gs * 16);
            cp_async16(sa + doff, Ag + (size_t)row * K + g * 8);
            cp_async16(sb + doff, Bg + (size_t)row * K + g * 8);
        }
        asm volatile("cp.async.commit_group;" ::: "memory");
    };

    // prologue
    #pragma unroll
    for (int s = 0; s < GSTG - 1; s++) load_stage(s, s);

    float acc[4][4][4];
    #pragma unroll
    for (int i = 0; i < 4; i++)
        #pragma unroll
        for (int j = 0; j < 4; j++)
            #pragma unroll
            for (int r = 0; r < 4; r++) acc[i][j][r] = 0.f;

    // ---- per-lane ldmatrix row geometry ----
    // A x4: q=lane>>3 -> (q&1) selects m-half (0/8), (q>>1) selects k-half (0/8)
    const int a_r     = ((lane >> 3) & 1) * 8 + (lane & 7);
    const int a_kpart = lane >> 4;                     // 0/1
    // B x4: (q>>1) selects n-half, (q&1) selects k-half
    const int b_r     = (lane >> 4) * 8 + (lane & 7);
    const int b_kpart = (lane >> 3) & 1;

    int aRow[4], aR7[4];
    #pragma unroll
    for (int mt = 0; mt < 4; mt++) {
        aRow[mt] = (m_w + mt * 16 + a_r) * 128;
        aR7[mt]  = (m_w + mt * 16 + a_r) & 7;
    }
    int bRow[2], bR7[2];
    #pragma unroll
    for (int ntp = 0; ntp < 2; ntp++) {
        bRow[ntp] = (n_w + ntp * 16 + b_r) * 128;
        bR7[ntp]  = (n_w + ntp * 16 + b_r) & 7;
    }

    uint32_t af[2][4][4];
    uint32_t bf[2][4][2];

    auto ldfrag = [&](int buf, uint32_t sa, uint32_t sb, int step) {
        const int gbase = step * 2;   // granule base: koff/8 = step*16/8
        #pragma unroll
        for (int mt = 0; mt < 4; mt++) {
            const uint32_t addr = sa + aRow[mt] + (((gbase + a_kpart) ^ aR7[mt]) << 4);
            ldsm_x4(af[buf][mt][0], af[buf][mt][1], af[buf][mt][2], af[buf][mt][3], addr);
        }
        #pragma unroll
        for (int ntp = 0; ntp < 2; ntp++) {
            const uint32_t addr = sb + bRow[ntp] + (((gbase + b_kpart) ^ bR7[ntp]) << 4);
            ldsm_x4(bf[buf][2*ntp][0], bf[buf][2*ntp][1],
                    bf[buf][2*ntp+1][0], bf[buf][2*ntp+1][1], addr);
        }
    };

    const int nst = K / GBK;
    for (int st = 0; st < nst; ++st) {
        asm volatile("cp.async.wait_group 1;" ::: "memory");
        __syncthreads();

        const int slot = st % GSTG;
        if (st + GSTG - 1 < nst) load_stage((st + GSTG - 1) % GSTG, st + GSTG - 1);
        else asm volatile("cp.async.commit_group;" ::: "memory");

        const uint32_t sa = smem_b + slot * STG_BYTES;
        const uint32_t sb = sa + 16384;

        ldfrag(0, sa, sb, 0);
        #pragma unroll
        for (int k16 = 0; k16 < 4; ++k16) {
            if (k16 < 3) ldfrag((k16 + 1) & 1, sa, sb, k16 + 1);
            const int buf = k16 & 1;
            #pragma unroll
            for (int mt = 0; mt < 4; mt++)
                #pragma unroll
                for (int nt = 0; nt < 4; nt++)
                    mma_f16_16816(acc[mt][nt], af[buf][mt], bf[buf][nt]);
        }
    }

    // epilogue: c0,c1 at (row gq, cols 2tg..); c2,c3 at row gq+8
    #pragma unroll
    for (int mt = 0; mt < 4; mt++) {
        const int r0 = m0 + m_w + mt * 16 + gq;
        #pragma unroll
        for (int nt = 0; nt < 4; nt++) {
            const int c0 = n0 + n_w + nt * 8 + tg * 2;
            *(float2*)&C[(size_t)r0 * N + c0]       = make_float2(acc[mt][nt][0], acc[mt][nt][1]);
            *(float2*)&C[(size_t)(r0 + 8) * N + c0] = make_float2(acc[mt][nt][2], acc[mt][nt][3]);
        }
    }
}

// ---------------- fp32 -> fp16 conversion ----------------
__global__ __launch_bounds__(256)
void tohalf_kernel(const float* __restrict__ in, __half* __restrict__ out, int n8)
{
    const int i = blockIdx.x * blockDim.x + threadIdx.x;
    if (i >= n8) return;
    const float4 r0 = ((const float4*)in)[2 * i];
    const float4 r1 = ((const float4*)in)[2 * i + 1];
    uint4 u;
    u.x = h2_bits(__floats2half2_rn(r0.x, r0.y));
    u.y = h2_bits(__floats2half2_rn(r0.z, r0.w));
    u.z = h2_bits(__floats2half2_rn(r1.x, r1.y));
    u.w = h2_bits(__floats2half2_rn(r1.z, r1.w));
    ((uint4*)out)[i] = u;
}

// ---------------- scan + sigmoid gate (reads fp32 xz, writes fp16 y) ----------------
__global__ __launch_bounds__(256)
void scan_gate_kernel(const float* __restrict__ A_log,
                      const float* __restrict__ xz,
                      __half* __restrict__ y)
{
    using namespace cfg;
    const int idx   = blockIdx.x * blockDim.x + threadIdx.x;
    const int inner = idx % INNER;
    const int bt    = idx / INNER;
    const int t     = bt % CHUNK;
    const int b     = bt / CHUNK;

    const float Ah = expf(-fabsf(A_log[inner >> 6]));
    float hstate = 0.f;

    size_t xrow = ((size_t)b * Ss + t) * (size_t)N1 + inner;
    size_t yrow = ((size_t)b * Ss + t) * (size_t)INNER + inner;
    const size_t xstep = (size_t)CHUNK * N1;
    const size_t ystep = (size_t)CHUNK * INNER;

    #pragma unroll
    for (int c = 0; c < NCH; c++) {
        const float xv = xz[xrow];
        const float zv = xz[xrow + INNER];
        hstate = hstate * Ah + 0.1f * xv;
        const float sig = 1.f / (1.f + expf(-zv));
        y[yrow] = __float2half_rn(hstate * sig);
        xrow += xstep;
        yrow += ystep;
    }
}

// ---------------- launch ----------------
extern "C" void kernel_launch(void* const* d_in, const int* in_sizes, int n_in,
                              void* d_out, int out_size)
{
    using namespace cfg;
    const float* hs    = (const float*)d_in[0];
    const float* W_in  = (const float*)d_in[1];
    const float* W_out = (const float*)d_in[2];
    const float* A_log = (const float*)d_in[3];
    float* out = (float*)d_out;

    float *xz;
    __half *yh, *a1h, *w1h, *w2h;
    cudaGetSymbolAddress((void**)&xz,  g_xz);
    cudaGetSymbolAddress((void**)&yh,  g_yh);
    cudaGetSymbolAddress((void**)&a1h, g_a1h);
    cudaGetSymbolAddress((void**)&w1h, g_w1h);
    cudaGetSymbolAddress((void**)&w2h, g_w2h);

    cudaFuncSetAttribute(gemm_f16, cudaFuncAttributeMaxDynamicSharedMemorySize, GSMEM_BYTES);

    // convert GEMM operands to fp16
    {
        int n8;
        n8 = (M1 * K1) / 8; tohalf_kernel<<<(n8 + 255) / 256, 256>>>(hs,    a1h, n8);
        n8 = (N1 * K1) / 8; tohalf_kernel<<<(n8 + 255) / 256, 256>>>(W_in,  w1h, n8);
        n8 = (N2 * K2) / 8; tohalf_kernel<<<(n8 + 255) / 256, 256>>>(W_out, w2h, n8);
    }

    // GEMM1: xz = hs @ W_in^T   (M=8192, N=14336, K=3584)
    gemm_f16<<<(M1 / GBM) * (N1 / GBN), 256, GSMEM_BYTES>>>(a1h, w1h, xz, M1, N1, K1);

    // scan + gate -> fp16 y
    const int total = Bb * CHUNK * INNER;
    scan_gate_kernel<<<total / 256, 256>>>(A_log, xz, yh);

    // GEMM2: out = y @ W_out^T  (M=8192, N=3584, K=7168)
    gemm_f16<<<(M1 / GBM) * (N2 / GBN), 256, GSMEM_BYTES>>>(yh, w2h, out, M1, N2, K2);
}

// round 10
// speedup vs baseline: 2.4466x; 1.0038x over previous
#include <cuda_runtime.h>
#include <cuda_fp16.h>
#include <cstdint>
#include <math.h>

// ---------------- problem constants ----------------
namespace cfg {
constexpr int Bb    = 2;
constexpr int Ss    = 4096;
constexpr int DM    = 3584;
constexpr int Hh    = 112;
constexpr int DH    = 64;
constexpr int CHUNK = 256;
constexpr int INNER = Hh * DH;          // 7168
constexpr int M1    = Bb * Ss;          // 8192
constexpr int N1    = 2 * INNER;        // 14336
constexpr int K1    = DM;               // 3584
constexpr int N2    = DM;               // 3584
constexpr int K2    = INNER;            // 7168
constexpr int NCH   = Ss / CHUNK;       // 16
}

// ---------------- scratch (no cudaMalloc allowed) ----------------
__device__ __half g_xzh[(size_t)cfg::M1 * cfg::N1];  // GEMM1 out (fp16)
__device__ __half g_yh [(size_t)cfg::M1 * cfg::K2];  // scan out (fp16)
__device__ __half g_a1h[(size_t)cfg::M1 * cfg::K1];  // hs    (fp16)
__device__ __half g_w1h[(size_t)cfg::N1 * cfg::K1];  // W_in  (fp16)
__device__ __half g_w2h[(size_t)cfg::N2 * cfg::K2];  // W_out (fp16)

// ---------------- helpers ----------------
__device__ __forceinline__ uint32_t smem_u32(const void* p) {
    uint32_t a;
    asm("{ .reg .u64 t; cvta.to.shared.u64 t, %1; cvt.u32.u64 %0, t; }" : "=r"(a) : "l"(p));
    return a;
}
__device__ __forceinline__ void cp_async16(uint32_t smem_addr, const void* gmem) {
    asm volatile("cp.async.cg.shared.global [%0], [%1], 16;" :: "r"(smem_addr), "l"(gmem) : "memory");
}
__device__ __forceinline__ void ldsm_x4(uint32_t& r0, uint32_t& r1, uint32_t& r2, uint32_t& r3,
                                        uint32_t addr) {
    asm volatile("ldmatrix.sync.aligned.m8n8.x4.shared.b16 {%0,%1,%2,%3}, [%4];"
                 : "=r"(r0), "=r"(r1), "=r"(r2), "=r"(r3) : "r"(addr));
}
__device__ __forceinline__ void mma_f16_16816(float d[4], const uint32_t a[4], const uint32_t b[2]) {
    asm volatile(
        "mma.sync.aligned.m16n8k16.row.col.f32.f16.f16.f32 "
        "{%0,%1,%2,%3}, {%4,%5,%6,%7}, {%8,%9}, {%0,%1,%2,%3};"
        : "+f"(d[0]), "+f"(d[1]), "+f"(d[2]), "+f"(d[3])
        : "r"(a[0]), "r"(a[1]), "r"(a[2]), "r"(a[3]),
          "r"(b[0]), "r"(b[1]));
}
__device__ __forceinline__ uint32_t h2_bits(__half2 h) {
    union { __half2 h; uint32_t u; } cvt;
    cvt.h = h;
    return cvt.u;
}

// ---------------- fp16 GEMM: C[M,N] = A[M,K] * B[N,K]^T (A,B fp16; C fp32 or fp16) ----------------
// BM=128, BN=128, BK=64 (128B rows, XOR-16B swizzle), 3-stage cp.async (96 KB),
// 256 threads, 8 warps 2x4 (warp tile 64x32), 2 CTAs/SM.
// Fragments via ldmatrix.x4; k16 steps register double-buffered.
#define GBM 128
#define GBN 128
#define GBK 64
#define STG_BYTES 32768                      // A 16KB + B 16KB
#define GSTG 3
#define GSMEM_BYTES (GSTG * STG_BYTES)       // 96 KB

template <typename OutT>
__global__ __launch_bounds__(256, 2)
void gemm_f16(const __half* __restrict__ A, const __half* __restrict__ B,
              OutT* __restrict__ C, int M, int N, int K)
{
    extern __shared__ char smem[];
    const uint32_t smem_b = smem_u32(smem);

    const int tid  = threadIdx.x;
    const int lane = tid & 31;
    const int wid  = tid >> 5;          // 0..7
    const int gq   = lane >> 2;         // 0..7
    const int tg   = lane & 3;          // 0..3
    const int m_w  = (wid >> 2) * 64;   // 2 warp rows
    const int n_w  = (wid & 3) * 32;    // 4 warp cols

    // ---- tile swizzle (grouped m for L2 reuse) ----
    const int nTm = M / GBM, nTn = N / GBN;
    constexpr int GROUP = 8;
    const int npg     = GROUP * nTn;
    const int gidx    = blockIdx.x / npg;
    const int first_m = gidx * GROUP;
    const int gsz     = min(nTm - first_m, GROUP);
    const int inG     = blockIdx.x % npg;
    const int m0 = (first_m + (inG % gsz)) * GBM;
    const int n0 = (inG / gsz) * GBN;

    // ---- cp.async fill mapping: 16B granules (8 fp16), 8 per 128B row ----
    const __half* Abase = A + (size_t)m0 * K;
    const __half* Bbase = B + (size_t)n0 * K;

    auto load_stage = [&](int slot, int st) {
        const uint32_t sa = smem_b + slot * STG_BYTES;
        const uint32_t sb = sa + 16384;
        const __half* Ag = Abase + st * GBK;
        const __half* Bg = Bbase + st * GBK;
        #pragma unroll
        for (int p = 0; p < 4; p++) {
            const int idx = tid + p * 256;      // 0..1023 granule id
            const int row = idx >> 3;           // 0..127
            const int g   = idx & 7;
            const int gs  = g ^ (row & 7);
            const uint32_t doff = (uint32_t)(row * 128 + gs * 16);
            cp_async16(sa + doff, Ag + (size_t)row * K + g * 8);
            cp_async16(sb + doff, Bg + (size_t)row * K + g * 8);
        }
        asm volatile("cp.async.commit_group;" ::: "memory");
    };

    // prologue
    #pragma unroll
    for (int s = 0; s < GSTG - 1; s++) load_stage(s, s);

    float acc[4][4][4];
    #pragma unroll
    for (int i = 0; i < 4; i++)
        #pragma unroll
        for (int j = 0; j < 4; j++)
            #pragma unroll
            for (int r = 0; r < 4; r++) acc[i][j][r] = 0.f;

    // ---- per-lane ldmatrix row geometry ----
    const int a_r     = ((lane >> 3) & 1) * 8 + (lane & 7);
    const int a_kpart = lane >> 4;                     // 0/1
    const int b_r     = (lane >> 4) * 8 + (lane & 7);
    const int b_kpart = (lane >> 3) & 1;

    int aRow[4], aR7[4];
    #pragma unroll
    for (int mt = 0; mt < 4; mt++) {
        aRow[mt] = (m_w + mt * 16 + a_r) * 128;
        aR7[mt]  = (m_w + mt * 16 + a_r) & 7;
    }
    int bRow[2], bR7[2];
    #pragma unroll
    for (int ntp = 0; ntp < 2; ntp++) {
        bRow[ntp] = (n_w + ntp * 16 + b_r) * 128;
        bR7[ntp]  = (n_w + ntp * 16 + b_r) & 7;
    }

    uint32_t af[2][4][4];
    uint32_t bf[2][4][2];

    auto ldfrag = [&](int buf, uint32_t sa, uint32_t sb, int step) {
        const int gbase = step * 2;
        #pragma unroll
        for (int mt = 0; mt < 4; mt++) {
            const uint32_t addr = sa + aRow[mt] + (((gbase + a_kpart) ^ aR7[mt]) << 4);
            ldsm_x4(af[buf][mt][0], af[buf][mt][1], af[buf][mt][2], af[buf][mt][3], addr);
        }
        #pragma unroll
        for (int ntp = 0; ntp < 2; ntp++) {
            const uint32_t addr = sb + bRow[ntp] + (((gbase + b_kpart) ^ bR7[ntp]) << 4);
            ldsm_x4(bf[buf][2*ntp][0], bf[buf][2*ntp][1],
                    bf[buf][2*ntp+1][0], bf[buf][2*ntp+1][1], addr);
        }
    };

    const int nst = K / GBK;
    for (int st = 0; st < nst; ++st) {
        asm volatile("cp.async.wait_group 1;" ::: "memory");
        __syncthreads();

        const int slot = st % GSTG;
        if (st + GSTG - 1 < nst) load_stage((st + GSTG - 1) % GSTG, st + GSTG - 1);
        else asm volatile("cp.async.commit_group;" ::: "memory");

        const uint32_t sa = smem_b + slot * STG_BYTES;
        const uint32_t sb = sa + 16384;

        ldfrag(0, sa, sb, 0);
        #pragma unroll
        for (int k16 = 0; k16 < 4; ++k16) {
            if (k16 < 3) ldfrag((k16 + 1) & 1, sa, sb, k16 + 1);
            const int buf = k16 & 1;
            #pragma unroll
            for (int mt = 0; mt < 4; mt++)
                #pragma unroll
                for (int nt = 0; nt < 4; nt++)
                    mma_f16_16816(acc[mt][nt], af[buf][mt], bf[buf][nt]);
        }
    }

    // epilogue: c0,c1 at (row gq, cols 2tg..); c2,c3 at row gq+8
    #pragma unroll
    for (int mt = 0; mt < 4; mt++) {
        const int r0 = m0 + m_w + mt * 16 + gq;
        #pragma unroll
        for (int nt = 0; nt < 4; nt++) {
            const int c0 = n0 + n_w + nt * 8 + tg * 2;
            if constexpr (sizeof(OutT) == 4) {
                *(float2*)&C[(size_t)r0 * N + c0]       = make_float2(acc[mt][nt][0], acc[mt][nt][1]);
                *(float2*)&C[(size_t)(r0 + 8) * N + c0] = make_float2(acc[mt][nt][2], acc[mt][nt][3]);
            } else {
                *(__half2*)&C[(size_t)r0 * N + c0]       = __floats2half2_rn(acc[mt][nt][0], acc[mt][nt][1]);
                *(__half2*)&C[(size_t)(r0 + 8) * N + c0] = __floats2half2_rn(acc[mt][nt][2], acc[mt][nt][3]);
            }
        }
    }
}

// ---------------- fp32 -> fp16 conversion ----------------
__global__ __launch_bounds__(256)
void tohalf_kernel(const float* __restrict__ in, __half* __restrict__ out, int n8)
{
    const int i = blockIdx.x * blockDim.x + threadIdx.x;
    if (i >= n8) return;
    const float4 r0 = ((const float4*)in)[2 * i];
    const float4 r1 = ((const float4*)in)[2 * i + 1];
    uint4 u;
    u.x = h2_bits(__floats2half2_rn(r0.x, r0.y));
    u.y = h2_bits(__floats2half2_rn(r0.z, r0.w));
    u.z = h2_bits(__floats2half2_rn(r1.x, r1.y));
    u.w = h2_bits(__floats2half2_rn(r1.z, r1.w));
    ((uint4*)out)[i] = u;
}

// ---------------- scan + sigmoid gate (reads fp16 xz, writes fp16 y) ----------------
__global__ __launch_bounds__(256)
void scan_gate_kernel(const float* __restrict__ A_log,
                      const __half* __restrict__ xz,
                      __half* __restrict__ y)
{
    using namespace cfg;
    const int idx   = blockIdx.x * blockDim.x + threadIdx.x;
    const int inner = idx % INNER;
    const int bt    = idx / INNER;
    const int t     = bt % CHUNK;
    const int b     = bt / CHUNK;

    const float Ah = expf(-fabsf(A_log[inner >> 6]));
    float hstate = 0.f;

    size_t xrow = ((size_t)b * Ss + t) * (size_t)N1 + inner;
    size_t yrow = ((size_t)b * Ss + t) * (size_t)INNER + inner;
    const size_t xstep = (size_t)CHUNK * N1;
    const size_t ystep = (size_t)CHUNK * INNER;

    #pragma unroll
    for (int c = 0; c < NCH; c++) {
        const float xv = __half2float(xz[xrow]);
        const float zv = __half2float(xz[xrow + INNER]);
        hstate = hstate * Ah + 0.1f * xv;
        const float sig = 1.f / (1.f + expf(-zv));
        y[yrow] = __float2half_rn(hstate * sig);
        xrow += xstep;
        yrow += ystep;
    }
}

// ---------------- launch ----------------
extern "C" void kernel_launch(void* const* d_in, const int* in_sizes, int n_in,
                              void* d_out, int out_size)
{
    using namespace cfg;
    const float* hs    = (const float*)d_in[0];
    const float* W_in  = (const float*)d_in[1];
    const float* W_out = (const float*)d_in[2];
    const float* A_log = (const float*)d_in[3];
    float* out = (float*)d_out;

    __half *xzh, *yh, *a1h, *w1h, *w2h;
    cudaGetSymbolAddress((void**)&xzh, g_xzh);
    cudaGetSymbolAddress((void**)&yh,  g_yh);
    cudaGetSymbolAddress((void**)&a1h, g_a1h);
    cudaGetSymbolAddress((void**)&w1h, g_w1h);
    cudaGetSymbolAddress((void**)&w2h, g_w2h);

    cudaFuncSetAttribute(gemm_f16<__half>, cudaFuncAttributeMaxDynamicSharedMemorySize, GSMEM_BYTES);
    cudaFuncSetAttribute(gemm_f16<float>,  cudaFuncAttributeMaxDynamicSharedMemorySize, GSMEM_BYTES);

    // convert GEMM operands to fp16
    {
        int n8;
        n8 = (M1 * K1) / 8; tohalf_kernel<<<(n8 + 255) / 256, 256>>>(hs,    a1h, n8);
        n8 = (N1 * K1) / 8; tohalf_kernel<<<(n8 + 255) / 256, 256>>>(W_in,  w1h, n8);
        n8 = (N2 * K2) / 8; tohalf_kernel<<<(n8 + 255) / 256, 256>>>(W_out, w2h, n8);
    }

    // GEMM1: xz = hs @ W_in^T   (M=8192, N=14336, K=3584) -> fp16
    gemm_f16<__half><<<(M1 / GBM) * (N1 / GBN), 256, GSMEM_BYTES>>>(a1h, w1h, xzh, M1, N1, K1);

    // scan + gate -> fp16 y
    const int total = Bb * CHUNK * INNER;
    scan_gate_kernel<<<total / 256, 256>>>(A_log, xzh, yh);

    // GEMM2: out = y @ W_out^T  (M=8192, N=3584, K=7168) -> fp32
    gemm_f16<float><<<(M1 / GBM) * (N2 / GBN), 256, GSMEM_BYTES>>>(yh, w2h, out, M1, N2, K2);
}